// round 15
// baseline (speedup 1.0000x reference)
#include <cuda_runtime.h>
#include <cuda_fp16.h>
#include <math.h>
#include <stdint.h>

#define B 8
#define H 8
#define T 8192
#define DH 64
#define BKT 128
#define BSZ 64
#define BH 64
#define HH 4
#define SCALE 0.04419417382415922f   /* (h*dh=512)^-0.5 */
#define NEG 3.402823466e38f
#define MASKV (-80.0f)

/* half-typed smem strides (in halves) */
#define QSH 72
#define K2H 72
#define PSH 136
#define V2H 72
/* byte offsets */
#define SMB_K2  9216
#define SMB_V2  17408
#define SMB_RED 35840
#define SMB_TOT 36352

/* scratch (no allocation allowed) */
__device__ float g_ps[BH * BKT * DH];   /* per-bucket sums */
__device__ float g_pe[BH * BKT * DH];   /* exclusive prefix of g_ps */
__device__ int   g_idx[BH * BKT];
__device__ float g_w[BH * BKT];

__device__ __forceinline__ uint32_t packh2(float a, float b) {
    __half2 h = __floats2half2_rn(a, b);
    return *(uint32_t*)&h;
}
__device__ __forceinline__ void mma_f16(float d[4], uint32_t a0, uint32_t a1,
                                        uint32_t a2, uint32_t a3,
                                        uint32_t b0, uint32_t b1) {
    asm("mma.sync.aligned.m16n8k16.row.col.f32.f16.f16.f32 "
        "{%0,%1,%2,%3}, {%4,%5,%6,%7}, {%8,%9}, {%0,%1,%2,%3};"
        : "+f"(d[0]), "+f"(d[1]), "+f"(d[2]), "+f"(d[3])
        : "r"(a0), "r"(a1), "r"(a2), "r"(a3), "r"(b0), "r"(b1));
}
__device__ __forceinline__ void ldsm_x2_t(uint32_t& r0, uint32_t& r1, uint32_t saddr) {
    asm volatile("ldmatrix.sync.aligned.m8n8.x2.trans.shared.b16 {%0,%1}, [%2];"
                 : "=r"(r0), "=r"(r1) : "r"(saddr));
}

/* ------------------------------------------------------------------ */
/* Stage A1: per-bucket sums of rotated K                              */
/* ------------------------------------------------------------------ */
__global__ void sc_stageA1(const float* __restrict__ k) {
    int u = blockIdx.x, bh = blockIdx.y;
    bool rot = (bh & 7) >= HH;
    __shared__ float P[4][DH];
    int tid = threadIdx.x;
    int d = tid & 63, part = tid >> 6;
    const float* kb = k + (size_t)bh * T * DH;
    int t0 = u * BSZ + part * 16;
    float s = 0.f;
#pragma unroll
    for (int j = 0; j < 16; ++j) {
        int tt = t0 + j;
        int rt = rot ? ((tt + 63) & (T - 1)) : tt;
        s += kb[(size_t)rt * DH + d];
    }
    P[part][d] = s;
    __syncthreads();
    if (part == 0)
        g_ps[((size_t)bh * BKT + u) * DH + d] = P[0][d] + P[1][d] + P[2][d] + P[3][d];
}

/* ------------------------------------------------------------------ */
/* Stage A2: exclusive prefix over buckets                             */
/* ------------------------------------------------------------------ */
__global__ void sc_stageA2() {
    int bh = blockIdx.x;
    int d = threadIdx.x;             /* 64 */
    const float* ps = g_ps + (size_t)bh * BKT * DH;
    float* pe = g_pe + (size_t)bh * BKT * DH;
    float run = 0.f;
#pragma unroll 8
    for (int u = 0; u < BKT; ++u) {
        pe[u * DH + d] = run;
        run += ps[u * DH + d];
    }
}

/* ------------------------------------------------------------------ */
/* Stage B: features (from g_pe) + sort-net logits -> top-1            */
/* grid (4, BH), 256 threads, 32 buckets/block, 4 buckets per warp     */
/* ------------------------------------------------------------------ */
__global__ void sc_stageB(const float* __restrict__ sortW,
                          const float* __restrict__ k) {
    extern __shared__ float sm[];
    float* Ws = sm;                  /* 16512 */
    float* xs = sm + 128 * 129;      /* 32*128 */
    int base = blockIdx.x * 32;
    int bh = blockIdx.y;
    int h = bh & 7;
    bool rot = h >= HH;
    int tid = threadIdx.x;           /* 256 */

    {
        const float4* Wh4 = (const float4*)(sortW + (size_t)h * 128 * 129);
        float4* Ws4 = (float4*)Ws;
        for (int i = tid; i < 4128; i += 256) Ws4[i] = Wh4[i];
    }
    /* features for this block's 32 buckets (direct prefix read) */
    {
        int d = tid & 63, p = tid >> 6;          /* p: 0..3, 8 buckets each */
        const float* pe = g_pe + (size_t)bh * BKT * DH;
        const float* kb = k + (size_t)bh * T * DH;
#pragma unroll
        for (int ul = p * 8; ul < p * 8 + 8; ++ul) {
            int ug = base + ul;
            int tt = ug * BSZ;
            int rt = rot ? ((tt + 63) & (T - 1)) : tt;
            float kf = kb[(size_t)rt * DH + d];
            float pv = pe[ug * DH + d];
            xs[ul * 128 + d]      = (pv + kf) / (float)(tt + 1);
            xs[ul * 128 + DH + d] = kf;
        }
    }
    __syncthreads();

    int warp = tid >> 5, lane = tid & 31;
    int b0 = 4 * warp;                           /* local buckets b0..b0+3 */
    int ngw = ((base + b0 + 3) >> 5) + 1;        /* groups any bucket needs */
    if (ngw > 4) ngw = 4;

    float acc[4][4];
#pragma unroll
    for (int bkt = 0; bkt < 4; ++bkt)
#pragma unroll
        for (int g = 0; g < 4; ++g) acc[bkt][g] = 0.f;

    for (int d = 0; d < 128; ++d) {
        const float* wrow = Ws + d * 129 + lane;
        float wv[4];
#pragma unroll
        for (int g = 0; g < 4; ++g)
            if (g < ngw) wv[g] = wrow[32 * g];
#pragma unroll
        for (int bkt = 0; bkt < 4; ++bkt) {
            float xv = xs[(b0 + bkt) * 128 + d];
#pragma unroll
            for (int g = 0; g < 4; ++g)
                if (g < ngw) acc[bkt][g] += xv * wv[g];
        }
    }

    /* per-bucket epilogue */
#pragma unroll
    for (int bkt = 0; bkt < 4; ++bkt) {
        int u = base + b0 + bkt;
        float v[4];
#pragma unroll
        for (int g = 0; g < 4; ++g) {
            int c = lane + 32 * g;
            float a = acc[bkt][g];
            v[g] = (g < ngw && c <= u) ? (a >= 0.f ? a : 0.01f * a) : -NEG;
        }
        float m = fmaxf(fmaxf(v[0], v[1]), fmaxf(v[2], v[3]));
        for (int off = 16; off >= 1; off >>= 1)
            m = fmaxf(m, __shfl_xor_sync(0xffffffffu, m, off));
        float s = 0.f;
#pragma unroll
        for (int g = 0; g < 4; ++g) s += __expf(v[g] - m);
        for (int off = 16; off >= 1; off >>= 1)
            s += __shfl_xor_sync(0xffffffffu, s, off);
        float bv = -NEG; int bi = 0;
#pragma unroll
        for (int g = 0; g < 4; ++g) {
            int c = lane + 32 * g;
            if (c < u && v[g] > bv) { bv = v[g]; bi = c; }
        }
        for (int off = 16; off >= 1; off >>= 1) {
            float ov = __shfl_xor_sync(0xffffffffu, bv, off);
            int   oi = __shfl_xor_sync(0xffffffffu, bi, off);
            if (ov > bv || (ov == bv && oi < bi)) { bv = ov; bi = oi; }
        }
        if (lane == 0) {
            float w = 0.f; int idx = 0;
            if (u > 0 && bv > -NEG) { w = __expf(bv - m) / s; idx = bi; }
            g_w[bh * BKT + u]   = w;
            g_idx[bh * BKT + u] = idx;
        }
    }
}

/* ------------------------------------------------------------------ */
/* Stage C: 64x128x64 attention via fp16 m16n8k16 MMA, 6 CTAs/SM      */
/* ------------------------------------------------------------------ */
__global__ void __launch_bounds__(128, 6) sc_stageC(
    const float* __restrict__ q, const float* __restrict__ k,
    const float* __restrict__ v, const float* __restrict__ nk,
    const float* __restrict__ nv, float* __restrict__ out) {
    extern __shared__ __align__(16) char smc[];
    __half* Qs = (__half*)smc;
    __half* K2 = (__half*)(smc + SMB_K2);
    __half* Ps = (__half*)smc;            /* overlay after S consumed */
    __half* V2 = (__half*)(smc + SMB_V2); /* filled after S consumed  */
    float* red = (float*)(smc + SMB_RED);

    int u = blockIdx.x, bh = blockIdx.y;
    int h = bh & 7;
    bool rot = h >= HH;
    int tid = threadIdx.x;           /* 128 */
    int t0 = u * BSZ;
    const float* qb = q + (size_t)bh * T * DH;
    const float* kb = k + (size_t)bh * T * DH;
    const float* vb = v + (size_t)bh * T * DH;

    int   ridx = g_idx[bh * BKT + u];
    float rw   = g_w[bh * BKT + u];

    /* phase0 fill: Q, local K (rows 64..127), routed K * w (rows 0..63) */
#pragma unroll
    for (int it = 0; it < 8; ++it) {
        int i = tid + 128 * it;
        int row = i >> 4, ch = i & 15;
        int tt = t0 + row;
        int rt = rot ? ((tt + 63) & (T - 1)) : tt;
        float4 q4 = *(const float4*)(qb + (size_t)rt * DH + ch * 4);
        *(uint2*)(Qs + row * QSH + ch * 4) =
            make_uint2(packh2(q4.x, q4.y), packh2(q4.z, q4.w));
        float4 k4 = *(const float4*)(kb + (size_t)rt * DH + ch * 4);
        *(uint2*)(K2 + (64 + row) * K2H + ch * 4) =
            make_uint2(packh2(k4.x, k4.y), packh2(k4.z, k4.w));
        float4 rk;
        if (ridx == 0) {
            rk = *(const float4*)(nk + h * DH + ch * 4);
        } else {
            int st = (ridx - 1) * BSZ + row;
            int srt = rot ? ((st + 63) & (T - 1)) : st;
            rk = *(const float4*)(kb + (size_t)srt * DH + ch * 4);
        }
        *(uint2*)(K2 + row * K2H + ch * 4) =
            make_uint2(packh2(rk.x * rw, rk.y * rw), packh2(rk.z * rw, rk.w * rw));
    }
    __syncthreads();

    int w  = tid >> 5, l = tid & 31;
    int wr = w & 1, wc = w >> 1;      /* 2x2 warp grid */
    int g  = l >> 2, lk = l & 3;
    int rbase = wr * 32;

    /* ---- S = Q K2^T ---- */
    float sa[2][8][4];
#pragma unroll
    for (int t = 0; t < 2; ++t)
#pragma unroll
        for (int nt = 0; nt < 8; ++nt)
#pragma unroll
            for (int j = 0; j < 4; ++j) sa[t][nt][j] = 0.f;

#pragma unroll
    for (int ck = 0; ck < 4; ++ck) {
        int kk = ck * 16;
        uint32_t a[2][4];
#pragma unroll
        for (int t = 0; t < 2; ++t) {
            int r0 = rbase + t * 16 + g;
            a[t][0] = *(const uint32_t*)(Qs + r0 * QSH + kk + 2 * lk);
            a[t][1] = *(const uint32_t*)(Qs + (r0 + 8) * QSH + kk + 2 * lk);
            a[t][2] = *(const uint32_t*)(Qs + r0 * QSH + kk + 2 * lk + 8);
            a[t][3] = *(const uint32_t*)(Qs + (r0 + 8) * QSH + kk + 2 * lk + 8);
        }
#pragma unroll
        for (int nt = 0; nt < 8; ++nt) {
            int krow = wc * 64 + nt * 8 + g;
            uint32_t b0 = *(const uint32_t*)(K2 + krow * K2H + kk + 2 * lk);
            uint32_t b1 = *(const uint32_t*)(K2 + krow * K2H + kk + 2 * lk + 8);
#pragma unroll
            for (int t = 0; t < 2; ++t)
                mma_f16(sa[t][nt], a[t][0], a[t][1], a[t][2], a[t][3], b0, b1);
        }
    }

    /* scale + mask + exp (no max subtraction: |logit| <~ 3 after scale) */
    bool special = rot && (u == BKT - 1);
#pragma unroll
    for (int t = 0; t < 2; ++t) {
        int r0 = rbase + t * 16 + g;
        float s0 = 0.f, s1 = 0.f;
#pragma unroll
        for (int nt = 0; nt < 8; ++nt) {
#pragma unroll
            for (int j = 0; j < 4; ++j) {
                int r = (j < 2) ? r0 : r0 + 8;
                int c = wc * 64 + nt * 8 + 2 * lk + (j & 1);
                bool ok = (c < BSZ) || (c - BSZ <= r);
                if (special && r >= 1 && c <= BSZ) ok = false;
                float p = __expf(ok ? sa[t][nt][j] * SCALE : MASKV);
                sa[t][nt][j] = p;
                if (j < 2) s0 += p; else s1 += p;
            }
        }
#pragma unroll
        for (int off = 1; off <= 2; off <<= 1) {
            s0 += __shfl_xor_sync(0xffffffffu, s0, off);
            s1 += __shfl_xor_sync(0xffffffffu, s1, off);
        }
        if (lk == 0) {
            red[r0 * 2 + wc] = s0;
            red[(r0 + 8) * 2 + wc] = s1;
        }
    }
    __syncthreads();
    /* Qs/K2 dead everywhere now */

    /* phase1 fill: V (rows 64..127), routed V * w (rows 0..63) */
#pragma unroll
    for (int it = 0; it < 8; ++it) {
        int i = tid + 128 * it;
        int row = i >> 4, ch = i & 15;
        int tt = t0 + row;
        int rt = rot ? ((tt + 63) & (T - 1)) : tt;
        float4 v4 = *(const float4*)(vb + (size_t)rt * DH + ch * 4);
        *(uint2*)(V2 + (64 + row) * V2H + ch * 4) =
            make_uint2(packh2(v4.x, v4.y), packh2(v4.z, v4.w));
        float4 rv;
        if (ridx == 0) {
            rv = *(const float4*)(nv + h * DH + ch * 4);
        } else {
            int st = (ridx - 1) * BSZ + row;
            int srt = rot ? ((st + 63) & (T - 1)) : st;
            rv = *(const float4*)(vb + (size_t)srt * DH + ch * 4);
        }
        *(uint2*)(V2 + row * V2H + ch * 4) =
            make_uint2(packh2(rv.x * rw, rv.y * rw), packh2(rv.z * rw, rv.w * rw));
    }

    /* write P (fp16) into overlay */
#pragma unroll
    for (int t = 0; t < 2; ++t) {
        int r0 = rbase + t * 16 + g;
        float inv0 = 1.f / (red[r0 * 2] + red[r0 * 2 + 1]);
        float inv1 = 1.f / (red[(r0 + 8) * 2] + red[(r0 + 8) * 2 + 1]);
#pragma unroll
        for (int nt = 0; nt < 8; ++nt) {
            int c = wc * 64 + nt * 8 + 2 * lk;
            *(uint32_t*)(Ps + r0 * PSH + c) =
                packh2(sa[t][nt][0] * inv0, sa[t][nt][1] * inv0);
            *(uint32_t*)(Ps + (r0 + 8) * PSH + c) =
                packh2(sa[t][nt][2] * inv1, sa[t][nt][3] * inv1);
        }
    }
    __syncthreads();

    /* ---- O = P V2 ---- */
    int dbase = wc * 32;
    uint32_t v2s = (uint32_t)__cvta_generic_to_shared(V2);
    int lrow = l & 15;
    float oa[2][4][4];
#pragma unroll
    for (int t = 0; t < 2; ++t)
#pragma unroll
        for (int nt = 0; nt < 4; ++nt)
#pragma unroll
            for (int j = 0; j < 4; ++j) oa[t][nt][j] = 0.f;

#pragma unroll
    for (int ck = 0; ck < 8; ++ck) {
        int kk = ck * 16;
        uint32_t a[2][4];
#pragma unroll
        for (int t = 0; t < 2; ++t) {
            int r0 = rbase + t * 16 + g;
            a[t][0] = *(const uint32_t*)(Ps + r0 * PSH + kk + 2 * lk);
            a[t][1] = *(const uint32_t*)(Ps + (r0 + 8) * PSH + kk + 2 * lk);
            a[t][2] = *(const uint32_t*)(Ps + r0 * PSH + kk + 2 * lk + 8);
            a[t][3] = *(const uint32_t*)(Ps + (r0 + 8) * PSH + kk + 2 * lk + 8);
        }
#pragma unroll
        for (int nt = 0; nt < 4; ++nt) {
            int dtile = dbase + nt * 8;
            uint32_t b0, b1;
            ldsm_x2_t(b0, b1, v2s + ((kk + lrow) * V2H + dtile) * 2);
#pragma unroll
            for (int t = 0; t < 2; ++t)
                mma_f16(oa[t][nt], a[t][0], a[t][1], a[t][2], a[t][3], b0, b1);
        }
    }

    /* store O with inverse head rotation */
#pragma unroll
    for (int t = 0; t < 2; ++t) {
        int r0 = rbase + t * 16 + g;
        int tt0 = t0 + r0;
        int rt0 = rot ? ((tt0 + 63) & (T - 1)) : tt0;
        int tt1 = t0 + r0 + 8;
        int rt1 = rot ? ((tt1 + 63) & (T - 1)) : tt1;
        float* ob0 = out + ((size_t)bh * T + rt0) * DH;
        float* ob1 = out + ((size_t)bh * T + rt1) * DH;
#pragma unroll
        for (int nt = 0; nt < 4; ++nt) {
            int c = dbase + nt * 8 + 2 * lk;
            *(float2*)(ob0 + c) = make_float2(oa[t][nt][0], oa[t][nt][1]);
            *(float2*)(ob1 + c) = make_float2(oa[t][nt][2], oa[t][nt][3]);
        }
    }
}

extern "C" void kernel_launch(void* const* d_in, const int* in_sizes, int n_in,
                              void* d_out, int out_size) {
    const float* q  = (const float*)d_in[0];
    const float* k  = (const float*)d_in[1];
    const float* v  = (const float*)d_in[2];
    const float* sW = (const float*)d_in[3];
    const float* nk = (const float*)d_in[4];
    const float* nv = (const float*)d_in[5];
    float* out = (float*)d_out;

    int smemB = (128 * 129 + 32 * 128) * 4;       /* 82432 B */
    int smemC = SMB_TOT;                          /* 36352 B */
    cudaFuncSetAttribute(sc_stageB, cudaFuncAttributeMaxDynamicSharedMemorySize, smemB);
    cudaFuncSetAttribute(sc_stageC, cudaFuncAttributeMaxDynamicSharedMemorySize, smemC);

    sc_stageA1<<<dim3(BKT, BH), 256>>>(k);
    sc_stageA2<<<BH, DH>>>();
    sc_stageB<<<dim3(4, BH), 256, smemB>>>(sW, k);
    sc_stageC<<<dim3(BKT, BH), 128, smemC>>>(q, k, v, nk, nv, out);
}